// round 15
// baseline (speedup 1.0000x reference)
#include <cuda_runtime.h>
#include <cstdint>

// RandomShiftsAug == integer pixel shift with edge clamp (reference's bilinear
// weights are exactly zero given its linspace/scale arithmetic):
//   out[n,c,j,i] = x[n,c, clamp(j+sy-PAD,0,H-1), clamp(i+sx-PAD,0,W-1)]
//
// R15 = R13 (direct register swizzle + 4/3-batched MLP, 33.4us) + L2
// residency steering on the input via createpolicy/cache_hint (the bare
// .L2::evict_last ld modifier is ptxas-restricted to 256-bit forms on
// sm_103; cache_hint has no such restriction). Input lines get evict_last
// priority so the output store stream evicts itself instead of the 115.6MB
// input (~62MB of measured re-fill DRAM traffic). Stores untouched.

#define C_   4
#define W_   84
#define H_   84
#define PAD_ 4
#define W4_  21
#define NBLK (H_ * W4_)   // 1764 quads per plane

__device__ __forceinline__ uint64_t mk_policy() {
    uint64_t pol;
    asm("createpolicy.fractional.L2::evict_last.b64 %0, 1.0;" : "=l"(pol));
    return pol;
}

__device__ __forceinline__ float4 ldg_el(const float4* p, uint64_t pol) {
    float4 v;
    asm volatile("ld.global.nc.L2::cache_hint.v4.f32 {%0, %1, %2, %3}, [%4], %5;"
                 : "=f"(v.x), "=f"(v.y), "=f"(v.z), "=f"(v.w)
                 : "l"(p), "l"(pol));
    return v;
}

__device__ __forceinline__ float sel4(const float4& A, int i) {
    return (i <= 0) ? A.x : (i == 1) ? A.y : (i == 2) ? A.z : A.w;
}

template <int CNT>
__device__ __forceinline__ void do_batch(
    int it0, int tid, int sx, int sy, int r, int d, uint64_t pol,
    const float4* __restrict__ plane, float4* __restrict__ oplane)
{
    float4 A[CNT], B[CNT];
    int ww[CNT], mm[CNT];

    #pragma unroll
    for (int i = 0; i < CNT; ++i) {
        int m  = tid + (it0 + i) * 256;
        bool ok = (m < NBLK);
        int ms = ok ? m : 0;
        int j  = ms / W4_;
        int w4 = ms - j * W4_;
        mm[i] = m; ww[i] = w4;

        int ys = min(max(j + sy, 0), H_ - 1);
        const float4* row = plane + ys * W4_;
        int q = min(max(w4 + d, 0), W4_ - 1);

        A[i] = ok ? ldg_el(row + q, pol) : make_float4(0.f, 0.f, 0.f, 0.f);
        if (r)
            B[i] = ok ? ldg_el(row + min(q + 1, W4_ - 1), pol) : A[i];
    }

    #pragma unroll
    for (int i = 0; i < CNT; ++i) {
        if (mm[i] < NBLK) {
            float4 v;
            if (r == 0)      v = A[i];
            else if (r == 1) v = make_float4(A[i].y, A[i].z, A[i].w, B[i].x);
            else if (r == 2) v = make_float4(A[i].z, A[i].w, B[i].x, B[i].y);
            else             v = make_float4(A[i].w, B[i].x, B[i].y, B[i].z);

            if (sx < 0 && ww[i] == 0) {
                // out[k] = in[max(k+sx,0)] = A[max(k+sx,0)]
                v.x = A[i].x;
                v.y = sel4(A[i], 1 + sx);
                v.z = sel4(A[i], 2 + sx);
                v.w = sel4(A[i], 3 + sx);
            } else if (sx > 0 && ww[i] == W4_ - 1) {
                // out[k] = in[80 + min(k+sx,3)] = A[min(k+sx,3)]
                v.x = sel4(A[i], min(0 + sx, 3));
                v.y = sel4(A[i], min(1 + sx, 3));
                v.z = sel4(A[i], min(2 + sx, 3));
                v.w = A[i].w;
            }
            oplane[mm[i]] = v;
        }
    }
}

__global__ void __launch_bounds__(256) shift_ilp_kernel(
    const float4* __restrict__ x4,
    const int*    __restrict__ shift,
    float4*       __restrict__ out4)
{
    const int nc  = blockIdx.x;        // n*C + c
    const int n   = nc >> 2;
    const int tid = threadIdx.x;

    int2 sh = __ldg(reinterpret_cast<const int2*>(shift) + n);
    const int sx = sh.x - PAD_;        // [-4, 4], uniform per image
    const int sy = sh.y - PAD_;
    const int r  = sx & 3;             // warp-uniform
    const int d  = (sx - r) >> 2;      // floor(sx/4) in {-1,0,1}

    const uint64_t pol = mk_policy();

    const float4* plane  = x4  + nc * NBLK;
    float4*       oplane = out4 + nc * NBLK;

    do_batch<4>(0, tid, sx, sy, r, d, pol, plane, oplane);
    do_batch<3>(4, tid, sx, sy, r, d, pol, plane, oplane);
}

extern "C" void kernel_launch(void* const* d_in, const int* in_sizes, int n_in,
                              void* d_out, int out_size)
{
    const float4* x4    = (const float4*)d_in[0];
    const int*    shift = (const int*)d_in[1];
    float4*       out4  = (float4*)d_out;

    int n = in_sizes[0] / (C_ * H_ * W_);
    shift_ilp_kernel<<<n * C_, 256>>>(x4, shift, out4);
}

// round 16
// speedup vs baseline: 1.1040x; 1.1040x over previous
#include <cuda_runtime.h>
#include <cstdint>

// RandomShiftsAug == integer pixel shift with edge clamp (reference's bilinear
// weights are exactly zero given its linspace/scale arithmetic):
//   out[n,c,j,i] = x[n,c, clamp(j+sy-PAD,0,H-1), clamp(i+sx-PAD,0,W-1)]
//
// R16 = R13 with the 4+3 load batches merged into ONE 7-deep batch: all A
// (and B when r!=0) LDG.128 issue back-to-back before any consume, doubling
// per-warp MLP (14 vs 8) and halving exposed-latency events per plane.
// Plain loads/stores (every cache-steering variant regressed: R11/R14/R15).

#define C_   4
#define W_   84
#define H_   84
#define PAD_ 4
#define W4_  21
#define NBLK (H_ * W4_)   // 1764 quads per plane

__device__ __forceinline__ float sel4(const float4& A, int i) {
    return (i <= 0) ? A.x : (i == 1) ? A.y : (i == 2) ? A.z : A.w;
}

__global__ void __launch_bounds__(256) shift_ilp_kernel(
    const float4* __restrict__ x4,
    const int*    __restrict__ shift,
    float4*       __restrict__ out4)
{
    const int nc  = blockIdx.x;        // n*C + c
    const int n   = nc >> 2;
    const int tid = threadIdx.x;

    int2 sh = __ldg(reinterpret_cast<const int2*>(shift) + n);
    const int sx = sh.x - PAD_;        // [-4, 4], uniform per image
    const int sy = sh.y - PAD_;
    const int r  = sx & 3;             // warp-uniform
    const int d  = (sx - r) >> 2;      // floor(sx/4) in {-1,0,1}

    const float4* plane  = x4  + nc * NBLK;
    float4*       oplane = out4 + nc * NBLK;

    float4 A[7], B[7];
    int ww[7];
    const bool tail_ok = (tid + 6 * 256) < NBLK;   // only it=6 can be OOB

    // ---- issue ALL loads back-to-back (MLP 7 or 14) ----
    #pragma unroll
    for (int i = 0; i < 7; ++i) {
        int m  = tid + i * 256;
        bool ok = (i < 6) | tail_ok;
        int ms = ok ? m : 0;
        int j  = ms / W4_;
        int w4 = ms - j * W4_;
        ww[i]  = w4;

        int ys = min(max(j + sy, 0), H_ - 1);
        const float4* row = plane + ys * W4_;
        int q = min(max(w4 + d, 0), W4_ - 1);

        A[i] = ok ? __ldg(row + q) : make_float4(0.f, 0.f, 0.f, 0.f);
        if (r)
            B[i] = ok ? __ldg(row + min(q + 1, W4_ - 1)) : A[i];
    }

    // ---- compose + store ----
    #pragma unroll
    for (int i = 0; i < 7; ++i) {
        if ((i < 6) | tail_ok) {
            float4 v;
            if (r == 0)      v = A[i];
            else if (r == 1) v = make_float4(A[i].y, A[i].z, A[i].w, B[i].x);
            else if (r == 2) v = make_float4(A[i].z, A[i].w, B[i].x, B[i].y);
            else             v = make_float4(A[i].w, B[i].x, B[i].y, B[i].z);

            if (sx < 0 && ww[i] == 0) {
                // out[k] = in[max(k+sx,0)] = A[max(k+sx,0)]
                v.x = A[i].x;
                v.y = sel4(A[i], 1 + sx);
                v.z = sel4(A[i], 2 + sx);
                v.w = sel4(A[i], 3 + sx);
            } else if (sx > 0 && ww[i] == W4_ - 1) {
                // out[k] = in[80 + min(k+sx,3)] = A[min(k+sx,3)]
                v.x = sel4(A[i], min(0 + sx, 3));
                v.y = sel4(A[i], min(1 + sx, 3));
                v.z = sel4(A[i], min(2 + sx, 3));
                v.w = A[i].w;
            }
            oplane[tid + i * 256] = v;
        }
    }
}

extern "C" void kernel_launch(void* const* d_in, const int* in_sizes, int n_in,
                              void* d_out, int out_size)
{
    const float4* x4    = (const float4*)d_in[0];
    const int*    shift = (const int*)d_in[1];
    float4*       out4  = (float4*)d_out;

    int n = in_sizes[0] / (C_ * H_ * W_);
    shift_ilp_kernel<<<n * C_, 256>>>(x4, shift, out4);
}